// round 1
// baseline (speedup 1.0000x reference)
#include <cuda_runtime.h>
#include <math.h>

#define B_    64
#define NR_   16384
#define IC_   16
#define NC_   10
#define OC_   16
#define CO_   160        // NC_*OC_
#define NS_   16         // K splits
#define KB_   1024       // NR_/NS_
#define RT_   16         // K tile
#define NTILES_ (KB_/RT_)

// ---------------- device scratch (no allocations allowed) ----------------
__device__ float g_xT[(size_t)IC_*NR_*B_];          // x transposed: [i][r][b]  (64 MB)
__device__ float g_upart[(size_t)IC_*NS_*CO_*B_];   // GEMM partials            (10.5 MB)
__device__ float g_uhat[IC_*CO_*B_];                // u_hat [i][co][b]
__device__ float g_v[B_*CO_];                       // v     [b][co]
__device__ float g_bij[IC_*NC_];                    // routing logits

// ---------------- helpers ----------------
__device__ __forceinline__ unsigned long long dup2(float x) {
    unsigned long long r;
    asm("mov.b64 %0, {%1, %1};" : "=l"(r) : "f"(x));
    return r;
}
__device__ __forceinline__ void ffma2(unsigned long long &d,
                                      unsigned long long a,
                                      unsigned long long b) {
    // packed fp32x2 FMA (Blackwell 2x fp32 path)
    asm("fma.rn.f32x2 %0, %1, %2, %0;" : "+l"(d) : "l"(a), "l"(b));
}
__device__ __forceinline__ void cp4(unsigned saddr, const float* g) {
    asm volatile("cp.async.ca.shared.global [%0], [%1], 4;" :: "r"(saddr), "l"(g));
}
__device__ __forceinline__ void cp16(unsigned saddr, const float* g) {
    asm volatile("cp.async.cg.shared.global [%0], [%1], 16;" :: "r"(saddr), "l"(g));
}

// ---------------- kernel 0: zero routing logits ----------------
__global__ void init_kernel() {
    int t = threadIdx.x;
    if (t < IC_*NC_) g_bij[t] = 0.f;
}

// ---------------- kernel 1: transpose x[b,r,i] -> xT[i][r][b] ----------------
__global__ __launch_bounds__(256) void transpose_kernel(const float* __restrict__ x) {
    __shared__ float s[8*16*65];            // [r][i][b] with pad-65 on b
    const int tid = threadIdx.x;
    const int r0  = blockIdx.x * 8;
    #pragma unroll
    for (int it = 0; it < 8; it++) {
        int idx = it*256 + tid;             // 2048 float4 loads total
        int iq = idx & 3, r = (idx >> 2) & 7, b = idx >> 5;
        float4 v = *(const float4*)(x + (size_t)b*NR_*IC_ + (size_t)(r0+r)*IC_ + iq*4);
        int base = (r*16 + iq*4)*65 + b;
        s[base] = v.x; s[base+65] = v.y; s[base+130] = v.z; s[base+195] = v.w;
    }
    __syncthreads();
    #pragma unroll
    for (int it = 0; it < 8; it++) {
        int idx = it*256 + tid;
        int b4 = idx & 15, i = (idx >> 4) & 15, r = idx >> 8;
        int base = (r*16 + i)*65 + b4*4;
        float4 v = make_float4(s[base], s[base+1], s[base+2], s[base+3]);
        *(float4*)(g_xT + (size_t)i*NR_*B_ + (size_t)(r0+r)*B_ + b4*4) = v;
    }
}

// ---------------- kernel 2: K-split GEMM, per i: C[co][b] += W[i,co,r]*xT[i][r][b] ----
__global__ __launch_bounds__(256, 2) void gemm_kernel(const float* __restrict__ W) {
    const int split = blockIdx.x;
    const int i     = blockIdx.y;
    const int tid   = threadIdx.x;

    __shared__ __align__(16) float w_sm[2][RT_][CO_+1];
    __shared__ __align__(16) float x_sm[2][RT_][B_];

    const float* Wb = W    + (size_t)(i*CO_)*NR_ + (size_t)split*KB_;
    const float* Xb = g_xT + (size_t)i*NR_*B_    + (size_t)(split*KB_)*B_;

    const int bx = tid & 7,  cy = tid >> 3;
    const int b0 = bx*8,     co0 = cy*5;

    unsigned long long acc[5][4];
    #pragma unroll
    for (int j = 0; j < 5; j++)
        #pragma unroll
        for (int k = 0; k < 4; k++) acc[j][k] = 0ull;

    auto load_tile = [&](int bf, int t) {
        const int roff = t*RT_;
        #pragma unroll
        for (int q = 0; q < 10; q++) {       // 2560 W floats
            int idx = tid + q*256;
            int co = idx >> 4, r = idx & 15;
            cp4((unsigned)__cvta_generic_to_shared(&w_sm[bf][r][co]),
                Wb + (size_t)co*NR_ + roff + r);
        }
        {                                     // 1024 x floats, 16B each
            int b4 = tid & 15, r = tid >> 4;
            cp16((unsigned)__cvta_generic_to_shared(&x_sm[bf][r][b4*4]),
                 Xb + (size_t)(roff + r)*B_ + b4*4);
        }
        asm volatile("cp.async.commit_group;" ::: "memory");
    };

    load_tile(0, 0);
    for (int t = 0; t < NTILES_; t++) {
        const int bf = t & 1;
        if (t + 1 < NTILES_) {
            load_tile(bf ^ 1, t + 1);
            asm volatile("cp.async.wait_group 1;" ::: "memory");
        } else {
            asm volatile("cp.async.wait_group 0;" ::: "memory");
        }
        __syncthreads();
        #pragma unroll
        for (int r = 0; r < RT_; r++) {
            ulonglong2 p0 = *(const ulonglong2*)&x_sm[bf][r][b0];
            ulonglong2 p1 = *(const ulonglong2*)&x_sm[bf][r][b0+4];
            unsigned long long x2[4] = {p0.x, p0.y, p1.x, p1.y};
            #pragma unroll
            for (int j = 0; j < 5; j++) {
                unsigned long long w2 = dup2(w_sm[bf][r][co0 + j]);
                #pragma unroll
                for (int k = 0; k < 4; k++) ffma2(acc[j][k], w2, x2[k]);
            }
        }
        __syncthreads();
    }

    float* out = g_upart + (size_t)(i*NS_ + split)*CO_*B_;
    #pragma unroll
    for (int j = 0; j < 5; j++)
        #pragma unroll
        for (int k = 0; k < 4; k++)
            *(unsigned long long*)&out[(size_t)(co0 + j)*B_ + b0 + 2*k] = acc[j][k];
}

// ---------------- kernel 3: reduce K-split partials ----------------
__global__ void reduce_kernel() {
    int gid = blockIdx.x*256 + threadIdx.x;        // 163840 outputs
    int i   = gid / (CO_*B_);
    int rem = gid % (CO_*B_);
    const float* p = g_upart + (size_t)i*NS_*CO_*B_ + rem;
    float s = 0.f;
    #pragma unroll
    for (int sp = 0; sp < NS_; sp++) s += p[(size_t)sp*CO_*B_];
    g_uhat[gid] = s;
}

// ---------------- kernel 4: softmax(b_ij) -> s_j -> v = squash(s) ----------------
__global__ void sv_kernel() {
    int gid = blockIdx.x*256 + threadIdx.x;        // 10240 = B_*CO_
    int b  = gid & 63;
    int co = gid >> 6;
    int c  = co >> 4;                              // co = c*16 + o
    float w[IC_];
    float m = -1e30f;
    #pragma unroll
    for (int ii = 0; ii < IC_; ii++) { w[ii] = g_bij[ii*NC_ + c]; m = fmaxf(m, w[ii]); }
    float sum = 0.f;
    #pragma unroll
    for (int ii = 0; ii < IC_; ii++) { w[ii] = expf(w[ii] - m); sum += w[ii]; }
    float s = 0.f;
    #pragma unroll
    for (int ii = 0; ii < IC_; ii++) s += w[ii] * g_uhat[(ii*CO_ + co)*B_ + b];
    s /= sum;
    float v = s * fabsf(s) / (1.f + s*s);          // s^3/((1+s^2)|s|)
    g_v[b*CO_ + co] = v;
}

// ---------------- kernel 5: agreement a_ij, deterministic tree reduce ----------------
__global__ void agree_kernel() {
    int i = blockIdx.x / NC_;
    int c = blockIdx.x % NC_;
    int tid = threadIdx.x;
    __shared__ float red[256];
    float p = 0.f;
    #pragma unroll
    for (int e = tid; e < OC_*B_; e += 256) {
        int o = e >> 6, b = e & 63;
        p += g_uhat[(i*CO_ + c*OC_ + o)*B_ + b] * g_v[b*CO_ + c*OC_ + o];
    }
    red[tid] = p; __syncthreads();
    for (int off = 128; off > 0; off >>= 1) {
        if (tid < off) red[tid] += red[tid + off];
        __syncthreads();
    }
    if (tid == 0) g_bij[i*NC_ + c] += red[0] * (1.0f / B_);
}

// ---------------- kernel 6: FC + sigmoid, copy v to output ----------------
__global__ void final_kernel(const float* __restrict__ fc_w,
                             const float* __restrict__ fc_b,
                             float* __restrict__ out) {
    if (blockIdx.x < 40) {
        int gid = blockIdx.x*256 + threadIdx.x;    // v: 10240 elements
        out[B_ + gid] = g_v[gid];                  // layout b*160 + c*16 + o matches
    } else {
        int b = threadIdx.x;
        if (b < B_) {
            float a = fc_b[0];
            for (int co = 0; co < CO_; co++) a += g_v[b*CO_ + co] * fc_w[co];
            out[b] = 1.f / (1.f + expf(-a));
        }
    }
}

// ---------------- launcher ----------------
extern "C" void kernel_launch(void* const* d_in, const int* in_sizes, int n_in,
                              void* d_out, int out_size) {
    const float* x    = (const float*)d_in[0];
    const float* W    = (const float*)d_in[1];
    const float* fc_w = (const float*)d_in[2];
    const float* fc_b = (const float*)d_in[3];
    float* out = (float*)d_out;

    init_kernel<<<1, 256>>>();
    transpose_kernel<<<NR_/8, 256>>>(x);
    gemm_kernel<<<dim3(NS_, IC_), 256>>>(W);
    reduce_kernel<<<(IC_*CO_*B_)/256, 256>>>();
    for (int it = 0; it < 3; it++) {
        sv_kernel<<<(B_*CO_)/256, 256>>>();
        if (it < 2) agree_kernel<<<IC_*NC_, 256>>>();
    }
    final_kernel<<<41, 256>>>(fc_w, fc_b, out);
}

// round 4
// speedup vs baseline: 1.5183x; 1.5183x over previous
#include <cuda_runtime.h>
#include <math.h>
#include <stdint.h>

#define B_    64
#define NR_   16384
#define IC_   16
#define NC_   10
#define OC_   16
#define CO_   160
#define NS_   16          // K splits (grid.x)
#define KB_   1024        // K per CTA
#define KT_   32          // K per stage
#define NT_   (KB_/KT_)   // 32 stages
#define PITCH 36          // floats per smem row (32 data + 4 pad)
#define STG_FLOATS ((B_ + CO_) * PITCH)   // 224*36 = 8064 floats / stage
#define SMEM_DYN   (3 * STG_FLOATS * 4)   // 96768 B

// ---------------- device scratch ----------------
__device__ float g_xK[(size_t)IC_*B_*NR_];          // [i][b][r], r contiguous
__device__ float g_upart[(size_t)IC_*NS_*B_*CO_];   // partials [i][split][b][co]
__device__ float g_uhat[IC_*B_*CO_];                // [i][b][co]
__device__ float g_v[B_*CO_];
__device__ float g_bij[IC_*NC_];

// ---------------- helpers ----------------
__device__ __forceinline__ uint32_t smem_u32(const void* p) {
    uint32_t a;
    asm("{ .reg .u64 t; cvta.to.shared.u64 t, %1; cvt.u32.u64 %0, t; }" : "=r"(a) : "l"(p));
    return a;
}
__device__ __forceinline__ void cp16(uint32_t saddr, const float* g) {
    asm volatile("cp.async.cg.shared.global [%0], [%1], 16;" :: "r"(saddr), "l"(g));
}
#define CP_COMMIT() asm volatile("cp.async.commit_group;" ::: "memory")
__device__ __forceinline__ uint32_t cvt_tf32(float x) {
    uint32_t r;
    asm("cvt.rna.tf32.f32 %0, %1;" : "=r"(r) : "f"(x));
    return r;
}
// split x into tf32 hi + tf32 lo (x ~= hi + lo, lo error ~2^-22|x|)
__device__ __forceinline__ void split_tf32(float x, uint32_t& hi, uint32_t& lo) {
    hi = cvt_tf32(x);
    lo = cvt_tf32(x - __uint_as_float(hi));
}
__device__ __forceinline__ void mma16n8k8(float* d, uint32_t a0, uint32_t a1,
                                          uint32_t a2, uint32_t a3,
                                          uint32_t b0, uint32_t b1) {
    asm("mma.sync.aligned.m16n8k8.row.col.f32.tf32.tf32.f32 "
        "{%0,%1,%2,%3},{%4,%5,%6,%7},{%8,%9},{%0,%1,%2,%3};"
        : "+f"(d[0]), "+f"(d[1]), "+f"(d[2]), "+f"(d[3])
        : "r"(a0), "r"(a1), "r"(a2), "r"(a3), "r"(b0), "r"(b1));
}

// ---------------- kernel 1: transpose x[b,r,i] -> xK[i][b][r] ----------------
__global__ __launch_bounds__(256) void transpose_kernel(const float* __restrict__ x) {
    __shared__ float s[4 * 16 * 129];           // [b4][i][r128] pad 129
    const int tid = threadIdx.x;
    const int r0 = blockIdx.x * 128, b0 = blockIdx.y * 4;
    if (blockIdx.x == 0 && blockIdx.y == 0 && tid < IC_ * NC_) g_bij[tid] = 0.f;
    #pragma unroll
    for (int it = 0; it < 8; it++) {
        int idx = it * 256 + tid;               // 2048 float4 over i
        int iq = idx & 3, r = (idx >> 2) & 127, b = idx >> 9;
        float4 v = *(const float4*)(x + ((size_t)(b0 + b) * NR_ + (r0 + r)) * IC_ + iq * 4);
        int base = (b * 16 + iq * 4) * 129 + r;
        s[base] = v.x; s[base + 129] = v.y; s[base + 258] = v.z; s[base + 387] = v.w;
    }
    __syncthreads();
    #pragma unroll
    for (int it = 0; it < 8; it++) {
        int idx = it * 256 + tid;               // 2048 float4 over r
        int rq = idx & 31, i = (idx >> 5) & 15, b = idx >> 9;
        int base = (b * 16 + i) * 129 + rq * 4;
        float4 v = make_float4(s[base], s[base + 1], s[base + 2], s[base + 3]);
        *(float4*)(g_xK + (size_t)(i * B_ + b0 + b) * NR_ + r0 + rq * 4) = v;
    }
}

// ---------------- kernel 2: mma.sync tf32x3 K-split GEMM ----------------
extern __shared__ float smf[];

__global__ __launch_bounds__(256, 2) void gemm_kernel(const float* __restrict__ W) {
    const int split = blockIdx.x, i = blockIdx.y;
    const int tid = threadIdx.x;
    const int wid = tid >> 5, lane = tid & 31;
    const int g = lane >> 2, c = lane & 3;
    const int mt = wid & 3;                     // m-tile (16 b rows)
    const int nh = wid >> 2;                    // n-half (80 co)
    const float* Wb = W    + (size_t)i * CO_ * NR_ + split * KB_;
    const float* Xb = g_xK + (size_t)i * B_  * NR_ + split * KB_;

    float acc[10][4];
    #pragma unroll
    for (int nt = 0; nt < 10; nt++)
        #pragma unroll
        for (int q = 0; q < 4; q++) acc[nt][q] = 0.f;

    auto load_stage = [&](int t) {
        float* st = smf + (t % 3) * STG_FLOATS;
        const int k0 = t * KT_;
        #pragma unroll
        for (int j = 0; j < 7; j++) {           // 1792 chunks of 16B
            int idx = tid + j * 256;
            int row = idx >> 3, ch = idx & 7;
            const float* src = (row < B_)
                ? Xb + (size_t)row * NR_ + k0 + ch * 4
                : Wb + (size_t)(row - B_) * NR_ + k0 + ch * 4;
            cp16(smem_u32(st + row * PITCH + ch * 4), src);
        }
        CP_COMMIT();
    };

    load_stage(0); load_stage(1); load_stage(2);

    for (int t = 0; t < NT_; t++) {
        if (t < NT_ - 2)       asm volatile("cp.async.wait_group 2;" ::: "memory");
        else if (t == NT_ - 2) asm volatile("cp.async.wait_group 1;" ::: "memory");
        else                   asm volatile("cp.async.wait_group 0;" ::: "memory");
        __syncthreads();
        const float* xs = smf + (t % 3) * STG_FLOATS;     // 64 rows [b][k]
        const float* ws = xs + B_ * PITCH;                // 160 rows [co][k]
        #pragma unroll
        for (int kk = 0; kk < 4; kk++) {
            const int kc = kk * 8 + c;
            uint32_t ah[4], al[4];
            split_tf32(xs[(mt * 16 + g)     * PITCH + kc],     ah[0], al[0]);
            split_tf32(xs[(mt * 16 + g + 8) * PITCH + kc],     ah[1], al[1]);
            split_tf32(xs[(mt * 16 + g)     * PITCH + kc + 4], ah[2], al[2]);
            split_tf32(xs[(mt * 16 + g + 8) * PITCH + kc + 4], ah[3], al[3]);
            #pragma unroll
            for (int nt = 0; nt < 10; nt++) {
                const int n = nh * 80 + nt * 8 + g;
                uint32_t bh0, bl0, bh1, bl1;
                split_tf32(ws[n * PITCH + kc],     bh0, bl0);
                split_tf32(ws[n * PITCH + kc + 4], bh1, bl1);
                mma16n8k8(acc[nt], ah[0], ah[1], ah[2], ah[3], bh0, bh1); // hi*hi
                mma16n8k8(acc[nt], ah[0], ah[1], ah[2], ah[3], bl0, bl1); // hi*lo
                mma16n8k8(acc[nt], al[0], al[1], al[2], al[3], bh0, bh1); // lo*hi
            }
        }
        __syncthreads();
        if (t + 3 < NT_) load_stage(t + 3);
    }

    // epilogue: D[row=b][col=co] fragments -> g_upart[i][split][b][co]
    float* outp = g_upart + (size_t)(i * NS_ + split) * B_ * CO_;
    const int row = mt * 16 + g;
    #pragma unroll
    for (int nt = 0; nt < 10; nt++) {
        const int col = nh * 80 + nt * 8 + 2 * c;
        *(float2*)(outp + (size_t)row * CO_ + col)       = make_float2(acc[nt][0], acc[nt][1]);
        *(float2*)(outp + (size_t)(row + 8) * CO_ + col) = make_float2(acc[nt][2], acc[nt][3]);
    }
}

// ---------------- kernel 3: reduce splits ----------------
__global__ void reduce_kernel() {
    int gid = blockIdx.x * 256 + threadIdx.x;   // 40960 float4
    int i = gid / 2560, rem = gid % 2560;
    const float4* p = (const float4*)(g_upart + (size_t)i * NS_ * B_ * CO_) + rem;
    float4 s = make_float4(0.f, 0.f, 0.f, 0.f);
    #pragma unroll
    for (int sp = 0; sp < NS_; sp++) {
        float4 v = p[(size_t)sp * (B_ * CO_ / 4)];
        s.x += v.x; s.y += v.y; s.z += v.z; s.w += v.w;
    }
    ((float4*)g_uhat)[gid] = s;
}

// ---------------- kernel 4: softmax + s_j + squash ----------------
__global__ void sv_kernel() {
    int gid = blockIdx.x * 256 + threadIdx.x;   // 10240 = B*CO
    int co = gid % CO_, b = gid / CO_;
    int c = co >> 4;
    float w[IC_]; float m = -1e30f;
    #pragma unroll
    for (int ii = 0; ii < IC_; ii++) { w[ii] = g_bij[ii * NC_ + c]; m = fmaxf(m, w[ii]); }
    float sum = 0.f;
    #pragma unroll
    for (int ii = 0; ii < IC_; ii++) { w[ii] = expf(w[ii] - m); sum += w[ii]; }
    float s = 0.f;
    #pragma unroll
    for (int ii = 0; ii < IC_; ii++) s += w[ii] * g_uhat[(ii * B_ + b) * CO_ + co];
    s /= sum;
    float v = s * fabsf(s) / (1.f + s * s);
    g_v[b * CO_ + co] = v;
}

// ---------------- kernel 5: agreement ----------------
__global__ void agree_kernel() {
    int i = blockIdx.x / NC_, c = blockIdx.x % NC_;
    int tid = threadIdx.x;
    __shared__ float red[256];
    float p = 0.f;
    #pragma unroll
    for (int e = tid; e < OC_ * B_; e += 256) {
        int o = e & 15, b = e >> 4;
        p += g_uhat[(i * B_ + b) * CO_ + c * 16 + o] * g_v[b * CO_ + c * 16 + o];
    }
    red[tid] = p; __syncthreads();
    for (int off = 128; off > 0; off >>= 1) {
        if (tid < off) red[tid] += red[tid + off];
        __syncthreads();
    }
    if (tid == 0) g_bij[i * NC_ + c] += red[0] * (1.0f / B_);
}

// ---------------- kernel 6: FC + sigmoid + v copy ----------------
__global__ void final_kernel(const float* __restrict__ fc_w,
                             const float* __restrict__ fc_b,
                             float* __restrict__ out) {
    if (blockIdx.x < 40) {
        int gid = blockIdx.x * 256 + threadIdx.x;
        out[B_ + gid] = g_v[gid];
    } else {
        int b = threadIdx.x;
        if (b < B_) {
            float a = fc_b[0];
            for (int co = 0; co < CO_; co++) a += g_v[b * CO_ + co] * fc_w[co];
            out[b] = 1.f / (1.f + expf(-a));
        }
    }
}

// ---------------- launcher ----------------
extern "C" void kernel_launch(void* const* d_in, const int* in_sizes, int n_in,
                              void* d_out, int out_size) {
    const float* x    = (const float*)d_in[0];
    const float* W    = (const float*)d_in[1];
    const float* fc_w = (const float*)d_in[2];
    const float* fc_b = (const float*)d_in[3];
    float* out = (float*)d_out;

    static int attr_done = 0;
    if (!attr_done) {
        cudaFuncSetAttribute(gemm_kernel, cudaFuncAttributeMaxDynamicSharedMemorySize, SMEM_DYN);
        attr_done = 1;
    }

    transpose_kernel<<<dim3(NR_ / 128, B_ / 4), 256>>>(x);
    gemm_kernel<<<dim3(NS_, IC_), 256, SMEM_DYN>>>(W);
    reduce_kernel<<<160, 256>>>();
    for (int it = 0; it < 3; it++) {
        sv_kernel<<<40, 256>>>();
        if (it < 2) agree_kernel<<<IC_ * NC_, 256>>>();
    }
    final_kernel<<<41, 256>>>(fc_w, fc_b, out);
}

// round 5
// speedup vs baseline: 2.3156x; 1.5252x over previous
#include <cuda_runtime.h>
#include <math.h>
#include <stdint.h>

#define B_    64
#define NR_   16384
#define IC_   16
#define NC_   10
#define OC_   16
#define CO_   160
#define NS_   16          // K splits (grid.x)
#define KB_   1024        // K per CTA
#define KT_   32          // K per stage
#define NT_   (KB_/KT_)   // 32 stages
#define PITCH 40          // floats per smem row (32 data + 8 pad) — conflict-free float2
#define STG_FLOATS ((B_ + CO_) * PITCH)   // 224*40 = 8960 floats / stage
#define SMEM_GEMM  (3 * STG_FLOATS * 4)   // 107520 B
#define SMEM_ROUT  ((IC_*B_*OC_ + B_*OC_ + 32) * 4)   // 69760 B

// ---------------- device scratch ----------------
__device__ float g_xK[(size_t)IC_*B_*NR_];          // [i][b][r], r contiguous
__device__ float g_upart[(size_t)IC_*NS_*B_*CO_];   // partials [i][split][b][co]
__device__ float g_uhat[IC_*B_*CO_];                // [i][b][co]
__device__ float g_v[B_*CO_];

// ---------------- helpers ----------------
__device__ __forceinline__ uint32_t smem_u32(const void* p) {
    uint32_t a;
    asm("{ .reg .u64 t; cvta.to.shared.u64 t, %1; cvt.u32.u64 %0, t; }" : "=r"(a) : "l"(p));
    return a;
}
__device__ __forceinline__ void cp16(uint32_t saddr, const float* g) {
    asm volatile("cp.async.cg.shared.global [%0], [%1], 16;" :: "r"(saddr), "l"(g));
}
#define CP_COMMIT() asm volatile("cp.async.commit_group;" ::: "memory")

// split packed pair (f0=k even, f1=k odd) into bf16x2 hi + bf16x2 lo
__device__ __forceinline__ void split_bf16x2(float f0, float f1, uint32_t& h, uint32_t& l) {
    asm("cvt.rn.satfinite.bf16x2.f32 %0, %1, %2;" : "=r"(h) : "f"(f1), "f"(f0));
    float g0 = __uint_as_float(h << 16);
    float g1 = __uint_as_float(h & 0xFFFF0000u);
    asm("cvt.rn.satfinite.bf16x2.f32 %0, %1, %2;" : "=r"(l) : "f"(f1 - g1), "f"(f0 - g0));
}
__device__ __forceinline__ void mma_bf16(float* d, const uint32_t* a,
                                         uint32_t b0, uint32_t b1) {
    asm("mma.sync.aligned.m16n8k16.row.col.f32.bf16.bf16.f32 "
        "{%0,%1,%2,%3},{%4,%5,%6,%7},{%8,%9},{%0,%1,%2,%3};"
        : "+f"(d[0]), "+f"(d[1]), "+f"(d[2]), "+f"(d[3])
        : "r"(a[0]), "r"(a[1]), "r"(a[2]), "r"(a[3]), "r"(b0), "r"(b1));
}

// ---------------- kernel 1: transpose x[b,r,i] -> xK[i][b][r] ----------------
__global__ __launch_bounds__(256) void transpose_kernel(const float* __restrict__ x) {
    __shared__ float s[4 * 16 * 129];           // [b4][i][r128] pad 129
    const int tid = threadIdx.x;
    const int r0 = blockIdx.x * 128, b0 = blockIdx.y * 4;
    #pragma unroll
    for (int it = 0; it < 8; it++) {
        int idx = it * 256 + tid;               // 2048 float4 over i
        int iq = idx & 3, r = (idx >> 2) & 127, b = idx >> 9;
        float4 v = *(const float4*)(x + ((size_t)(b0 + b) * NR_ + (r0 + r)) * IC_ + iq * 4);
        int base = (b * 16 + iq * 4) * 129 + r;
        s[base] = v.x; s[base + 129] = v.y; s[base + 258] = v.z; s[base + 387] = v.w;
    }
    __syncthreads();
    #pragma unroll
    for (int it = 0; it < 8; it++) {
        int idx = it * 256 + tid;               // 2048 float4 over r
        int rq = idx & 31, i = (idx >> 5) & 15, b = idx >> 9;
        int base = (b * 16 + i) * 129 + rq * 4;
        float4 v = make_float4(s[base], s[base + 1], s[base + 2], s[base + 3]);
        *(float4*)(g_xK + (size_t)(i * B_ + b0 + b) * NR_ + r0 + rq * 4) = v;
    }
}

// ---------------- kernel 2: mma.sync bf16x3 K-split GEMM ----------------
extern __shared__ float smf[];

__global__ __launch_bounds__(256, 2) void gemm_kernel(const float* __restrict__ W) {
    const int split = blockIdx.x, i = blockIdx.y;
    const int tid = threadIdx.x;
    const int wid = tid >> 5, lane = tid & 31;
    const int g = lane >> 2, c = lane & 3;
    const int mt = wid & 1;                     // m-tile (32 b rows)
    const int ng = wid >> 1;                    // n-group (40 co)
    const float* Wb = W    + (size_t)i * CO_ * NR_ + split * KB_;
    const float* Xb = g_xK + (size_t)i * B_  * NR_ + split * KB_;

    float acc[2][5][4];
    #pragma unroll
    for (int t = 0; t < 2; t++)
        #pragma unroll
        for (int nt = 0; nt < 5; nt++)
            #pragma unroll
            for (int q = 0; q < 4; q++) acc[t][nt][q] = 0.f;

    auto load_stage = [&](int t) {
        float* st = smf + (t % 3) * STG_FLOATS;
        const int k0 = t * KT_;
        #pragma unroll
        for (int j = 0; j < 7; j++) {           // 1792 chunks of 16B
            int idx = tid + j * 256;
            int row = idx >> 3, ch = idx & 7;
            const float* src = (row < B_)
                ? Xb + (size_t)row * NR_ + k0 + ch * 4
                : Wb + (size_t)(row - B_) * NR_ + k0 + ch * 4;
            cp16(smem_u32(st + row * PITCH + ch * 4), src);
        }
        CP_COMMIT();
    };

    load_stage(0); load_stage(1); load_stage(2);

    for (int t = 0; t < NT_; t++) {
        if (t < NT_ - 2)       asm volatile("cp.async.wait_group 2;" ::: "memory");
        else if (t == NT_ - 2) asm volatile("cp.async.wait_group 1;" ::: "memory");
        else                   asm volatile("cp.async.wait_group 0;" ::: "memory");
        __syncthreads();
        const float* xs = smf + (t % 3) * STG_FLOATS;     // 64 rows [b][k]
        const float* ws = xs + B_ * PITCH;                // 160 rows [co][k]
        #pragma unroll
        for (int kk = 0; kk < 2; kk++) {
            const int kc = kk * 16;
            // A fragments: 2 sub-tiles of m16
            uint32_t ah[2][4], al[2][4];
            #pragma unroll
            for (int st2 = 0; st2 < 2; st2++) {
                const int rb = mt * 32 + st2 * 16;
                float2 p00 = *(const float2*)&xs[(rb + g)     * PITCH + kc + 2 * c];
                float2 p10 = *(const float2*)&xs[(rb + g + 8) * PITCH + kc + 2 * c];
                float2 p01 = *(const float2*)&xs[(rb + g)     * PITCH + kc + 2 * c + 8];
                float2 p11 = *(const float2*)&xs[(rb + g + 8) * PITCH + kc + 2 * c + 8];
                split_bf16x2(p00.x, p00.y, ah[st2][0], al[st2][0]);
                split_bf16x2(p10.x, p10.y, ah[st2][1], al[st2][1]);
                split_bf16x2(p01.x, p01.y, ah[st2][2], al[st2][2]);
                split_bf16x2(p11.x, p11.y, ah[st2][3], al[st2][3]);
            }
            #pragma unroll
            for (int nt = 0; nt < 5; nt++) {
                const int n = ng * 40 + nt * 8 + g;
                float2 q0 = *(const float2*)&ws[n * PITCH + kc + 2 * c];
                float2 q1 = *(const float2*)&ws[n * PITCH + kc + 2 * c + 8];
                uint32_t bh0, bl0, bh1, bl1;
                split_bf16x2(q0.x, q0.y, bh0, bl0);
                split_bf16x2(q1.x, q1.y, bh1, bl1);
                #pragma unroll
                for (int st2 = 0; st2 < 2; st2++) {
                    mma_bf16(acc[st2][nt], ah[st2], bh0, bh1);   // hi*hi
                    mma_bf16(acc[st2][nt], ah[st2], bl0, bl1);   // hi*lo
                    mma_bf16(acc[st2][nt], al[st2], bh0, bh1);   // lo*hi
                }
            }
        }
        __syncthreads();
        if (t + 3 < NT_) load_stage(t + 3);
    }

    // epilogue -> g_upart[i][split][b][co]
    float* outp = g_upart + (size_t)(i * NS_ + split) * B_ * CO_;
    #pragma unroll
    for (int st2 = 0; st2 < 2; st2++) {
        const int row = mt * 32 + st2 * 16 + g;
        #pragma unroll
        for (int nt = 0; nt < 5; nt++) {
            const int col = ng * 40 + nt * 8 + 2 * c;
            *(float2*)(outp + (size_t)row * CO_ + col)       = make_float2(acc[st2][nt][0], acc[st2][nt][1]);
            *(float2*)(outp + (size_t)(row + 8) * CO_ + col) = make_float2(acc[st2][nt][2], acc[st2][nt][3]);
        }
    }
}

// ---------------- kernel 3: reduce splits ----------------
__global__ void reduce_kernel() {
    int gid = blockIdx.x * 256 + threadIdx.x;   // 40960 float4
    int i = gid / 2560, rem = gid % 2560;
    const float4* p = (const float4*)(g_upart + (size_t)i * NS_ * B_ * CO_) + rem;
    float4 s = make_float4(0.f, 0.f, 0.f, 0.f);
    #pragma unroll
    for (int sp = 0; sp < NS_; sp++) {
        float4 v = p[(size_t)sp * (B_ * CO_ / 4)];
        s.x += v.x; s.y += v.y; s.z += v.z; s.w += v.w;
    }
    ((float4*)g_uhat)[gid] = s;
}

// ---------------- kernel 4: fused routing (one CTA per capsule column c) ----
extern __shared__ float rsm[];
__global__ __launch_bounds__(512) void routing_kernel() {
    const int c = blockIdx.x;
    const int tid = threadIdx.x;
    float* su = rsm;                       // [i][b][o] 16x64x16
    float* sv = rsm + IC_ * B_ * OC_;      // [b][o]    64x16
    float* sb = sv + B_ * OC_;             // bij col (16)
    float* sc = sb + IC_;                  // softmax  (16)

    // load uhat slice for column c
    #pragma unroll
    for (int j = 0; j < 8; j++) {
        int idx = tid + j * 512;           // 4096 float4
        int i = idx >> 8, rem = idx & 255; // rem = b*4 + oq
        int b = rem >> 2, oq = rem & 3;
        float4 v = *(const float4*)(g_uhat + ((i * B_ + b) * CO_) + c * OC_ + oq * 4);
        *(float4*)(su + (i * B_ + b) * OC_ + oq * 4) = v;
    }
    if (tid < IC_) sb[tid] = 0.f;
    __syncthreads();

    for (int it = 0; it < 3; it++) {
        if (tid == 0) {                    // softmax over i (16 values)
            float m = -1e30f;
            #pragma unroll
            for (int i = 0; i < IC_; i++) m = fmaxf(m, sb[i]);
            float sum = 0.f;
            #pragma unroll
            for (int i = 0; i < IC_; i++) { float e = expf(sb[i] - m); sc[i] = e; sum += e; }
            float inv = 1.f / sum;
            #pragma unroll
            for (int i = 0; i < IC_; i++) sc[i] *= inv;
        }
        __syncthreads();
        #pragma unroll
        for (int e = tid; e < B_ * OC_; e += 512) {   // s_j + squash
            float s = 0.f;
            #pragma unroll
            for (int i = 0; i < IC_; i++) s += sc[i] * su[i * B_ * OC_ + e];
            sv[e] = s * fabsf(s) / (1.f + s * s);
        }
        __syncthreads();
        if (it < 2) {                      // agreement: warp w handles i=w
            int i = tid >> 5, lane = tid & 31;
            float p = 0.f;
            #pragma unroll
            for (int e = lane; e < B_ * OC_; e += 32)
                p += su[i * B_ * OC_ + e] * sv[e];
            #pragma unroll
            for (int off = 16; off > 0; off >>= 1)
                p += __shfl_xor_sync(0xFFFFFFFF, p, off);
            if (lane == 0) sb[i] += p * (1.f / B_);
            __syncthreads();
        }
    }
    for (int e = tid; e < B_ * OC_; e += 512)
        g_v[(e >> 4) * CO_ + c * OC_ + (e & 15)] = sv[e];
}

// ---------------- kernel 5: FC + sigmoid + v copy ----------------
__global__ void final_kernel(const float* __restrict__ fc_w,
                             const float* __restrict__ fc_b,
                             float* __restrict__ out) {
    if (blockIdx.x < 40) {
        int gid = blockIdx.x * 256 + threadIdx.x;
        out[B_ + gid] = g_v[gid];
    } else {
        int b = threadIdx.x;
        if (b < B_) {
            float a = fc_b[0];
            for (int co = 0; co < CO_; co++) a += g_v[b * CO_ + co] * fc_w[co];
            out[b] = 1.f / (1.f + expf(-a));
        }
    }
}

// ---------------- launcher ----------------
extern "C" void kernel_launch(void* const* d_in, const int* in_sizes, int n_in,
                              void* d_out, int out_size) {
    const float* x    = (const float*)d_in[0];
    const float* W    = (const float*)d_in[1];
    const float* fc_w = (const float*)d_in[2];
    const float* fc_b = (const float*)d_in[3];
    float* out = (float*)d_out;

    static int attr_done = 0;
    if (!attr_done) {
        cudaFuncSetAttribute(gemm_kernel, cudaFuncAttributeMaxDynamicSharedMemorySize, SMEM_GEMM);
        cudaFuncSetAttribute(routing_kernel, cudaFuncAttributeMaxDynamicSharedMemorySize, SMEM_ROUT);
        attr_done = 1;
    }

    transpose_kernel<<<dim3(NR_ / 128, B_ / 4), 256>>>(x);
    gemm_kernel<<<dim3(NS_, IC_), 256, SMEM_GEMM>>>(W);
    reduce_kernel<<<160, 256>>>();
    routing_kernel<<<NC_, 512, SMEM_ROUT>>>();
    final_kernel<<<41, 256>>>(fc_w, fc_b, out);
}

// round 6
// speedup vs baseline: 2.5452x; 1.0992x over previous
#include <cuda_runtime.h>
#include <math.h>
#include <stdint.h>

#define B_    64
#define NR_   16384
#define IC_   16
#define NC_   10
#define OC_   16
#define CO_   160
#define NS_   16          // K splits (grid.x)
#define KB_   1024        // K per CTA
#define KT_   32          // K per stage
#define NT_   (KB_/KT_)   // 32 stages
#define PITCH_A 20        // u32 per A smem row (16 pairs + 4 pad)
#define PITCH_W 40        // floats per W smem row (32 + 8 pad)
#define NPAIR   (NR_/2)   // 8192 bf16x2 pairs per (i,b)
// stage layout (u32 units): [A_hi 64*20][A_lo 64*20][W 160*40]
#define STG_FLOATS (64*PITCH_A + 64*PITCH_A + CO_*PITCH_W)   // 8960
#define SMEM_GEMM  (3 * STG_FLOATS * 4)                      // 107520 B
#define SMEM_ROUT  ((IC_*B_*OC_ + B_*OC_ + 48) * 4)

// ---------------- device scratch ----------------
__device__ uint32_t g_xh[(size_t)IC_*B_*NPAIR];     // x hi bf16x2 [i][b][rpair]
__device__ uint32_t g_xl[(size_t)IC_*B_*NPAIR];     // x lo bf16x2
__device__ float g_upart[(size_t)IC_*NS_*B_*CO_];   // partials [i][split][b][co]
__device__ float g_uhatC[NC_*IC_*B_*OC_];           // uhat [c][i][b][o]
__device__ float g_v[B_*CO_];

// ---------------- helpers ----------------
__device__ __forceinline__ uint32_t smem_u32(const void* p) {
    uint32_t a;
    asm("{ .reg .u64 t; cvta.to.shared.u64 t, %1; cvt.u32.u64 %0, t; }" : "=r"(a) : "l"(p));
    return a;
}
__device__ __forceinline__ void cp16(uint32_t saddr, const void* g) {
    asm volatile("cp.async.cg.shared.global [%0], [%1], 16;" :: "r"(saddr), "l"(g));
}
#define CP_COMMIT() asm volatile("cp.async.commit_group;" ::: "memory")

// split packed pair (f0=k even, f1=k odd) into bf16x2 hi + bf16x2 lo
__device__ __forceinline__ void split_bf16x2(float f0, float f1, uint32_t& h, uint32_t& l) {
    asm("cvt.rn.satfinite.bf16x2.f32 %0, %1, %2;" : "=r"(h) : "f"(f1), "f"(f0));
    float g0 = __uint_as_float(h << 16);
    float g1 = __uint_as_float(h & 0xFFFF0000u);
    asm("cvt.rn.satfinite.bf16x2.f32 %0, %1, %2;" : "=r"(l) : "f"(f1 - g1), "f"(f0 - g0));
}
__device__ __forceinline__ void mma_bf16(float* d, const uint32_t* a,
                                         uint32_t b0, uint32_t b1) {
    asm("mma.sync.aligned.m16n8k16.row.col.f32.bf16.bf16.f32 "
        "{%0,%1,%2,%3},{%4,%5,%6,%7},{%8,%9},{%0,%1,%2,%3};"
        : "+f"(d[0]), "+f"(d[1]), "+f"(d[2]), "+f"(d[3])
        : "r"(a[0]), "r"(a[1]), "r"(a[2]), "r"(a[3]), "r"(b0), "r"(b1));
}

// ---------------- kernel 1: transpose+split x[b,r,i] -> xh/xl[i][b][rpair] ----
__global__ __launch_bounds__(256) void transpose_kernel(const float* __restrict__ x) {
    __shared__ float s[4 * 16 * 129];           // [b4][i][r128] pad 129
    const int tid = threadIdx.x;
    const int r0 = blockIdx.x * 128, b0 = blockIdx.y * 4;
    #pragma unroll
    for (int it = 0; it < 8; it++) {
        int idx = it * 256 + tid;               // 2048 float4 over i
        int iq = idx & 3, r = (idx >> 2) & 127, b = idx >> 9;
        float4 v = *(const float4*)(x + ((size_t)(b0 + b) * NR_ + (r0 + r)) * IC_ + iq * 4);
        int base = (b * 16 + iq * 4) * 129 + r;
        s[base] = v.x; s[base + 129] = v.y; s[base + 258] = v.z; s[base + 387] = v.w;
    }
    __syncthreads();
    #pragma unroll
    for (int it = 0; it < 8; it++) {
        int idx = it * 256 + tid;               // 2048 groups of 4 r
        int rq = idx & 31, i = (idx >> 5) & 15, b = idx >> 9;
        int base = (b * 16 + i) * 129 + rq * 4;
        uint32_t h0, l0, h1, l1;
        split_bf16x2(s[base],     s[base + 1], h0, l0);
        split_bf16x2(s[base + 2], s[base + 3], h1, l1);
        size_t po = (size_t)(i * B_ + b0 + b) * NPAIR + (r0 >> 1) + rq * 2;
        *(uint2*)(g_xh + po) = make_uint2(h0, h1);
        *(uint2*)(g_xl + po) = make_uint2(l0, l1);
    }
}

// ---------------- kernel 2: mma.sync bf16x3 K-split GEMM ----------------
extern __shared__ float smf[];

__global__ __launch_bounds__(256, 2) void gemm_kernel(const float* __restrict__ W) {
    const int split = blockIdx.x, i = blockIdx.y;
    const int tid = threadIdx.x;
    const int wid = tid >> 5, lane = tid & 31;
    const int g = lane >> 2, c = lane & 3;
    const int mt = wid & 1;                     // m-tile (32 b rows)
    const int ng = wid >> 1;                    // n-group (40 co)
    const float* Wb = W + (size_t)i * CO_ * NR_ + split * KB_;
    const size_t ib = (size_t)i * B_;

    float acc[2][5][4];
    #pragma unroll
    for (int t = 0; t < 2; t++)
        #pragma unroll
        for (int nt = 0; nt < 5; nt++)
            #pragma unroll
            for (int q = 0; q < 4; q++) acc[t][nt][q] = 0.f;

    auto load_stage = [&](int t) {
        uint32_t sbase = smem_u32(smf + (t % 3) * STG_FLOATS);
        const int p0 = split * (KB_ / 2) + t * (KT_ / 2);   // pair offset
        const int k0 = split * KB_ + t * KT_ - split * KB_; // k within Wb handled below
        #pragma unroll
        for (int j = 0; j < 7; j++) {           // 1792 chunks of 16B
            int idx = tid + j * 256;
            if (idx < 512) {
                int half = idx >> 8, r2 = idx & 255;
                int row = r2 >> 2, ch = r2 & 3;
                const uint32_t* src = (half ? g_xl : g_xh) + (ib + row) * NPAIR + p0 + ch * 4;
                cp16(sbase + (half * 1280 + row * PITCH_A + ch * 4) * 4, src);
            } else {
                int idx2 = idx - 512;
                int row = idx2 >> 3, ch = idx2 & 7;
                cp16(sbase + (2560 + row * PITCH_W + ch * 4) * 4,
                     Wb + (size_t)row * NR_ + t * KT_ + ch * 4);
            }
        }
        CP_COMMIT();
        (void)k0;
    };

    load_stage(0); load_stage(1); load_stage(2);

    for (int t = 0; t < NT_; t++) {
        if (t < NT_ - 2)       asm volatile("cp.async.wait_group 2;" ::: "memory");
        else if (t == NT_ - 2) asm volatile("cp.async.wait_group 1;" ::: "memory");
        else                   asm volatile("cp.async.wait_group 0;" ::: "memory");
        __syncthreads();
        const uint32_t* xh = (const uint32_t*)(smf + (t % 3) * STG_FLOATS);
        const uint32_t* xl = xh + 1280;
        const float*    ws = (const float*)(xh + 2560);
        #pragma unroll
        for (int kk = 0; kk < 2; kk++) {
            uint32_t ah[2][4], al[2][4];
            #pragma unroll
            for (int st2 = 0; st2 < 2; st2++) {
                const int rb = mt * 32 + st2 * 16;
                const int cA = kk * 8 + c;
                ah[st2][0] = xh[(rb + g)     * PITCH_A + cA];
                ah[st2][1] = xh[(rb + g + 8) * PITCH_A + cA];
                ah[st2][2] = xh[(rb + g)     * PITCH_A + cA + 4];
                ah[st2][3] = xh[(rb + g + 8) * PITCH_A + cA + 4];
                al[st2][0] = xl[(rb + g)     * PITCH_A + cA];
                al[st2][1] = xl[(rb + g + 8) * PITCH_A + cA];
                al[st2][2] = xl[(rb + g)     * PITCH_A + cA + 4];
                al[st2][3] = xl[(rb + g + 8) * PITCH_A + cA + 4];
            }
            const int kc = kk * 16;
            #pragma unroll
            for (int nt = 0; nt < 5; nt++) {
                const int n = ng * 40 + nt * 8 + g;
                float2 q0 = *(const float2*)&ws[n * PITCH_W + kc + 2 * c];
                float2 q1 = *(const float2*)&ws[n * PITCH_W + kc + 2 * c + 8];
                uint32_t bh0, bl0, bh1, bl1;
                split_bf16x2(q0.x, q0.y, bh0, bl0);
                split_bf16x2(q1.x, q1.y, bh1, bl1);
                #pragma unroll
                for (int st2 = 0; st2 < 2; st2++) {
                    mma_bf16(acc[st2][nt], ah[st2], bh0, bh1);   // hi*hi
                    mma_bf16(acc[st2][nt], ah[st2], bl0, bl1);   // hi*lo
                    mma_bf16(acc[st2][nt], al[st2], bh0, bh1);   // lo*hi
                }
            }
        }
        __syncthreads();
        if (t + 3 < NT_) load_stage(t + 3);
    }

    // epilogue -> g_upart[i][split][b][co]
    float* outp = g_upart + (size_t)(i * NS_ + split) * B_ * CO_;
    #pragma unroll
    for (int st2 = 0; st2 < 2; st2++) {
        const int row = mt * 32 + st2 * 16 + g;
        #pragma unroll
        for (int nt = 0; nt < 5; nt++) {
            const int col = ng * 40 + nt * 8 + 2 * c;
            *(float2*)(outp + (size_t)row * CO_ + col)       = make_float2(acc[st2][nt][0], acc[st2][nt][1]);
            *(float2*)(outp + (size_t)(row + 8) * CO_ + col) = make_float2(acc[st2][nt][2], acc[st2][nt][3]);
        }
    }
}

// ---------------- kernel 3: reduce splits -> uhat[c][i][b][o] ----------------
__global__ void reduce_kernel() {
    int gid = blockIdx.x * 256 + threadIdx.x;   // 40960 float4
    int oq = gid & 3, b = (gid >> 2) & 63, i = (gid >> 8) & 15, c = gid >> 12;
    const float* p = g_upart + ((size_t)(i * NS_) * B_ + b) * CO_ + c * OC_ + oq * 4;
    float4 s = make_float4(0.f, 0.f, 0.f, 0.f);
    #pragma unroll
    for (int sp = 0; sp < NS_; sp++) {
        float4 v = *(const float4*)(p + (size_t)sp * B_ * CO_);
        s.x += v.x; s.y += v.y; s.z += v.z; s.w += v.w;
    }
    ((float4*)g_uhatC)[gid] = s;
}

// ---------------- kernel 4: fused routing (one CTA per capsule column c) ----
extern __shared__ float rsm[];
__global__ __launch_bounds__(1024) void routing_kernel(float* __restrict__ out) {
    const int c = blockIdx.x;
    const int tid = threadIdx.x;
    float* su = rsm;                       // [i][b*o] 16x1024
    float* sv = rsm + IC_ * 1024;          // [b*o] 1024
    float* sb = sv + 1024;                 // bij col (16)
    float* sc = sb + IC_;                  // softmax  (16)

    // load uhat slice for column c: contiguous 64 KB
    const float4* src = (const float4*)(g_uhatC + c * IC_ * 1024);
    #pragma unroll
    for (int j = 0; j < 4; j++)
        ((float4*)su)[tid + j * 1024] = src[tid + j * 1024];
    if (tid < IC_) sb[tid] = 0.f;
    __syncthreads();

    for (int it = 0; it < 3; it++) {
        if (tid == 0) {                    // softmax over i (16 values)
            float m = -1e30f;
            #pragma unroll
            for (int i = 0; i < IC_; i++) m = fmaxf(m, sb[i]);
            float sum = 0.f;
            #pragma unroll
            for (int i = 0; i < IC_; i++) { float e = expf(sb[i] - m); sc[i] = e; sum += e; }
            float inv = 1.f / sum;
            #pragma unroll
            for (int i = 0; i < IC_; i++) sc[i] *= inv;
        }
        __syncthreads();
        {                                  // s_j + squash, one element/thread
            float s = 0.f;
            #pragma unroll
            for (int i = 0; i < IC_; i++) s += sc[i] * su[i * 1024 + tid];
            sv[tid] = s * fabsf(s) / (1.f + s * s);
        }
        __syncthreads();
        if (it < 2) {                      // agreement: warp w handles i=w (w<16)
            int i = tid >> 5, lane = tid & 31;
            if (i < IC_) {
                float p = 0.f;
                #pragma unroll
                for (int j = 0; j < 32; j++) {
                    int e = lane + j * 32;
                    p += su[i * 1024 + e] * sv[e];
                }
                #pragma unroll
                for (int off = 16; off > 0; off >>= 1)
                    p += __shfl_xor_sync(0xFFFFFFFF, p, off);
                if (lane == 0) sb[i] += p * (1.f / B_);
            }
            __syncthreads();
        }
    }
    // write v slice to output tensor and to g_v for the FC head
    int b = tid >> 4, o = tid & 15;
    float v = sv[tid];
    out[B_ + b * CO_ + c * OC_ + o] = v;
    g_v[b * CO_ + c * OC_ + o] = v;
}

// ---------------- kernel 5: FC + sigmoid (pred only) ----------------
__global__ __launch_bounds__(1024) void final_kernel(const float* __restrict__ fc_w,
                                                     const float* __restrict__ fc_b,
                                                     float* __restrict__ out) {
    int tid = threadIdx.x;
    int b = tid >> 4, j = tid & 15;
    float p = 0.f;
    #pragma unroll
    for (int q = 0; q < 10; q++) {
        int co = j + q * 16;
        p += g_v[b * CO_ + co] * fc_w[co];
    }
    #pragma unroll
    for (int off = 8; off > 0; off >>= 1)
        p += __shfl_xor_sync(0xFFFFFFFF, p, off, 16);
    if (j == 0) out[b] = 1.f / (1.f + expf(-(p + fc_b[0])));
}

// ---------------- launcher ----------------
extern "C" void kernel_launch(void* const* d_in, const int* in_sizes, int n_in,
                              void* d_out, int out_size) {
    const float* x    = (const float*)d_in[0];
    const float* W    = (const float*)d_in[1];
    const float* fc_w = (const float*)d_in[2];
    const float* fc_b = (const float*)d_in[3];
    float* out = (float*)d_out;

    static int attr_done = 0;
    if (!attr_done) {
        cudaFuncSetAttribute(gemm_kernel, cudaFuncAttributeMaxDynamicSharedMemorySize, SMEM_GEMM);
        cudaFuncSetAttribute(routing_kernel, cudaFuncAttributeMaxDynamicSharedMemorySize, SMEM_ROUT);
        attr_done = 1;
    }

    transpose_kernel<<<dim3(NR_ / 128, B_ / 4), 256>>>(x);
    gemm_kernel<<<dim3(NS_, IC_), 256, SMEM_GEMM>>>(W);
    reduce_kernel<<<160, 256>>>();
    routing_kernel<<<NC_, 1024, SMEM_ROUT>>>(out);
    final_kernel<<<1, 1024>>>(fc_w, fc_b, out);
}